// round 3
// baseline (speedup 1.0000x reference)
#include <cuda_runtime.h>
#include <math.h>

#define MAXN 100000
#define MAXE 3200000

// ---------------- scratch (static device globals; no allocation) -------------
__device__ float g_hs1 [(size_t)MAXN * 128]; // scaled X@W1
__device__ float g_h2s [(size_t)MAXN * 64];  // scaled h1@W2 (from fused gather)
__device__ float g_h2  [(size_t)MAXN * 64];  // h2 (post conv2)
__device__ float g_s   [(size_t)MAXN * 8];   // exp(attention logits)
__device__ float g_dinv[MAXN];               // deg^{-1/2}
__device__ int   g_cnt [MAXN];               // edge in-degree (no self loop)
__device__ int   g_tmp [MAXN];               // block-inclusive scan values
__device__ int   g_off [MAXN + 1];           // CSR offsets
__device__ int   g_cur [MAXN];               // bucket cursors
__device__ int   g_ecsr[MAXE];               // src ids grouped by dst
__device__ int   g_bsum[128];
__device__ int   g_bpre[128];
__device__ float g_Zstage[512];              // 64-way spread Z partials [64][8]
__device__ float g_G[512];                   // unnormalized att.T @ h2  [8,64]
__device__ float g_C[64];                    // unnormalized att.T @ att [8,8]

// ---------------- init / degree / CSR build ----------------------------------
__global__ void k_init(int n) {
    int i = blockIdx.x * blockDim.x + threadIdx.x;
    if (i < n)   g_cnt[i] = 0;
    if (i < 512) { g_G[i] = 0.0f; g_Zstage[i] = 0.0f; }
    if (i < 64)  g_C[i] = 0.0f;
}

__global__ void k_deg(const int* __restrict__ dst, int e) {
    int i = blockIdx.x * blockDim.x + threadIdx.x;
    if (i < e) atomicAdd(&g_cnt[dst[i]], 1);
}

__global__ void k_scan1(int n) {
    __shared__ int sh[1024];
    int i = blockIdx.x * 1024 + threadIdx.x;
    int v = (i < n) ? g_cnt[i] : 0;
    if (i < n) g_dinv[i] = rsqrtf((float)(v + 1)); // +1 self loop
    sh[threadIdx.x] = v;
    __syncthreads();
#pragma unroll
    for (int off = 1; off < 1024; off <<= 1) {
        int t = (threadIdx.x >= off) ? sh[threadIdx.x - off] : 0;
        __syncthreads();
        sh[threadIdx.x] += t;
        __syncthreads();
    }
    if (i < n) g_tmp[i] = sh[threadIdx.x];
    if (threadIdx.x == 1023) g_bsum[blockIdx.x] = sh[1023];
}

__global__ void k_scan2(int nb) {
    if (threadIdx.x == 0) {
        int run = 0;
        for (int b = 0; b < nb; b++) { g_bpre[b] = run; run += g_bsum[b]; }
    }
}

__global__ void k_scan3(int n) {
    int i = blockIdx.x * 1024 + threadIdx.x;
    if (i < n) {
        int inc = g_tmp[i] + g_bpre[blockIdx.x];
        g_off[i + 1] = inc;
        g_cur[i]     = inc - g_cnt[i];
    }
    if (i == 0) g_off[0] = 0;
}

__global__ void k_bucket(const int* __restrict__ src, const int* __restrict__ dst, int e) {
    int i = blockIdx.x * blockDim.x + threadIdx.x;
    if (i < e) {
        int d   = dst[i];
        int pos = atomicAdd(&g_cur[d], 1);
        g_ecsr[pos] = src[i];
    }
}

// ---------------- register-tiled fp32 GEMM (layer 1 only) ---------------------
// out[i,:] = (A[i,:] @ W) * dinv[i]
__global__ void gemm1_kernel(const float* __restrict__ A,
                             const float* __restrict__ W,
                             float* __restrict__ out0, int n) {
    constexpr int K = 128, C = 128;
    constexpr int BM = 128, TN = 4;
    constexpr int NCG = C / TN;      // 32
    constexpr int NRG = 256 / NCG;   // 8
    constexpr int TM  = BM / NRG;    // 16
    constexpr int KC  = 32;

    __shared__ float Ash[BM * KC];
    __shared__ float Bsh[KC * C];

    int tid = threadIdx.x;
    int m0  = blockIdx.x * BM;
    int tc  = tid % NCG;
    int tr  = tid / NCG;

    float acc[TM][TN];
#pragma unroll
    for (int i = 0; i < TM; i++)
#pragma unroll
        for (int j = 0; j < TN; j++) acc[i][j] = 0.0f;

    for (int kc = 0; kc < K; kc += KC) {
        constexpr int AF4 = BM * KC / 4;
#pragma unroll
        for (int t = tid; t < AF4; t += 256) {
            int r  = t / (KC / 4);
            int c4 = t % (KC / 4);
            float4 v = make_float4(0.f, 0.f, 0.f, 0.f);
            int row = m0 + r;
            if (row < n)
                v = *reinterpret_cast<const float4*>(&A[(size_t)row * K + kc + c4 * 4]);
            *reinterpret_cast<float4*>(&Ash[r * KC + c4 * 4]) = v;
        }
        constexpr int BF4 = KC * C / 4;
#pragma unroll
        for (int t = tid; t < BF4; t += 256) {
            int r  = t / (C / 4);
            int c4 = t % (C / 4);
            *reinterpret_cast<float4*>(&Bsh[r * C + c4 * 4]) =
                *reinterpret_cast<const float4*>(&W[(size_t)(kc + r) * C + c4 * 4]);
        }
        __syncthreads();
#pragma unroll
        for (int k4 = 0; k4 < KC / 4; k4++) {
            float4 b0 = *reinterpret_cast<const float4*>(&Bsh[(k4 * 4 + 0) * C + tc * TN]);
            float4 b1 = *reinterpret_cast<const float4*>(&Bsh[(k4 * 4 + 1) * C + tc * TN]);
            float4 b2 = *reinterpret_cast<const float4*>(&Bsh[(k4 * 4 + 2) * C + tc * TN]);
            float4 b3 = *reinterpret_cast<const float4*>(&Bsh[(k4 * 4 + 3) * C + tc * TN]);
#pragma unroll
            for (int i = 0; i < TM; i++) {
                float4 a = *reinterpret_cast<const float4*>(&Ash[(tr * TM + i) * KC + k4 * 4]);
                acc[i][0] += a.x * b0.x + a.y * b1.x + a.z * b2.x + a.w * b3.x;
                acc[i][1] += a.x * b0.y + a.y * b1.y + a.z * b2.y + a.w * b3.y;
                acc[i][2] += a.x * b0.z + a.y * b1.z + a.z * b2.z + a.w * b3.z;
                acc[i][3] += a.x * b0.w + a.y * b1.w + a.z * b2.w + a.w * b3.w;
            }
        }
        __syncthreads();
    }

#pragma unroll
    for (int i = 0; i < TM; i++) {
        int row = m0 + tr * TM + i;
        if (row >= n) continue;
        float sc = g_dinv[row];
        float4 o = make_float4(acc[i][0] * sc, acc[i][1] * sc,
                               acc[i][2] * sc, acc[i][3] * sc);
        *reinterpret_cast<float4*>(&out0[(size_t)row * C + tc * TN]) = o;
    }
}

// ---------------- fused gather1 + GEMV W2 -------------------------------------
// warp per node: agg = hs1[node] + sum hs1[src]; h1 = relu(agg*dinv + b1)
// h2s[node] = (h1 @ W2) * dinv[node]
__global__ void gather128_fused(const float* __restrict__ hs,
                                const float* __restrict__ b1,
                                const float* __restrict__ W2,
                                float* __restrict__ h2s, int n) {
    __shared__ float W2sh[128 * 64];  // 32KB
    __shared__ float h1sh[8][128];    // 4KB
    int tid = threadIdx.x;
    for (int t = tid; t < 128 * 64 / 4; t += 256)
        *reinterpret_cast<float4*>(&W2sh[t * 4]) =
            *reinterpret_cast<const float4*>(&W2[t * 4]);
    __syncthreads();

    int w    = tid >> 5;
    int lane = tid & 31;
    int node = blockIdx.x * 8 + w;
    if (node >= n) return;

    float4 acc = *reinterpret_cast<const float4*>(&hs[(size_t)node * 128 + lane * 4]);
    int j = g_off[node], jend = g_off[node + 1];
    for (; j + 2 <= jend; j += 2) {
        int s0 = __ldg(&g_ecsr[j]);
        int s1 = __ldg(&g_ecsr[j + 1]);
        float4 v0 = *reinterpret_cast<const float4*>(&hs[(size_t)s0 * 128 + lane * 4]);
        float4 v1 = *reinterpret_cast<const float4*>(&hs[(size_t)s1 * 128 + lane * 4]);
        acc.x += v0.x + v1.x; acc.y += v0.y + v1.y;
        acc.z += v0.z + v1.z; acc.w += v0.w + v1.w;
    }
    if (j < jend) {
        int s0 = __ldg(&g_ecsr[j]);
        float4 v0 = *reinterpret_cast<const float4*>(&hs[(size_t)s0 * 128 + lane * 4]);
        acc.x += v0.x; acc.y += v0.y; acc.z += v0.z; acc.w += v0.w;
    }
    float di = g_dinv[node];
    float4 bb = *reinterpret_cast<const float4*>(&b1[lane * 4]);
    float4 h1;
    h1.x = fmaxf(acc.x * di + bb.x, 0.f);
    h1.y = fmaxf(acc.y * di + bb.y, 0.f);
    h1.z = fmaxf(acc.z * di + bb.z, 0.f);
    h1.w = fmaxf(acc.w * di + bb.w, 0.f);
    *reinterpret_cast<float4*>(&h1sh[w][lane * 4]) = h1;
    __syncwarp();

    // GEMV: each lane computes cols 2*lane, 2*lane+1 of h1 @ W2  (W2: [128,64])
    float s0 = 0.f, s1 = 0.f;
#pragma unroll 4
    for (int k = 0; k < 128; k++) {
        float h = h1sh[w][k];
        float2 wv = *reinterpret_cast<const float2*>(&W2sh[k * 64 + 2 * lane]);
        s0 += h * wv.x;
        s1 += h * wv.y;
    }
    float2 o = make_float2(s0 * di, s1 * di);
    *reinterpret_cast<float2*>(&h2s[(size_t)node * 64 + 2 * lane]) = o;
}

// ---------------- fused gather2 + attention MLP --------------------------------
// warp per node: h2 = agg(h2s)*dinv + b2 ; a1 = tanh(h2@Wf1+bf1);
// es = exp(a1@Wf2+bf2); store h2, es; accumulate Z into spread staging.
__global__ void gather64_fused(const float* __restrict__ h2s,
                               const float* __restrict__ b2,
                               const float* __restrict__ Wf1,
                               const float* __restrict__ bf1,
                               const float* __restrict__ Wf2,
                               const float* __restrict__ bf2,
                               float* __restrict__ h2out, int n) {
    __shared__ float Wf1sh[64 * 64];   // 16KB  [k][c]
    __shared__ float Wf2t[8 * 64];     // 2KB   transposed [d][j]
    __shared__ float rowsh[8][64];     // 2KB
    int tid = threadIdx.x;
    for (int t = tid; t < 64 * 64 / 4; t += 256)
        *reinterpret_cast<float4*>(&Wf1sh[t * 4]) =
            *reinterpret_cast<const float4*>(&Wf1[t * 4]);
    for (int t = tid; t < 512; t += 256) {
        int jj = t >> 3, dd = t & 7;
        Wf2t[dd * 64 + jj] = Wf2[jj * 8 + dd];
    }
    __syncthreads();

    int w    = tid >> 5;
    int lane = tid & 31;
    int node = blockIdx.x * 8 + w;
    if (node >= n) return;

    float2 acc = *reinterpret_cast<const float2*>(&h2s[(size_t)node * 64 + lane * 2]);
    int j = g_off[node], jend = g_off[node + 1];
    for (; j + 2 <= jend; j += 2) {
        int s0 = __ldg(&g_ecsr[j]);
        int s1 = __ldg(&g_ecsr[j + 1]);
        float2 v0 = *reinterpret_cast<const float2*>(&h2s[(size_t)s0 * 64 + lane * 2]);
        float2 v1 = *reinterpret_cast<const float2*>(&h2s[(size_t)s1 * 64 + lane * 2]);
        acc.x += v0.x + v1.x; acc.y += v0.y + v1.y;
    }
    if (j < jend) {
        int s0 = __ldg(&g_ecsr[j]);
        float2 v0 = *reinterpret_cast<const float2*>(&h2s[(size_t)s0 * 64 + lane * 2]);
        acc.x += v0.x; acc.y += v0.y;
    }
    float di = g_dinv[node];
    float2 bb = *reinterpret_cast<const float2*>(&b2[lane * 2]);
    float2 h2 = make_float2(acc.x * di + bb.x, acc.y * di + bb.y);
    *reinterpret_cast<float2*>(&h2out[(size_t)node * 64 + lane * 2]) = h2;
    *reinterpret_cast<float2*>(&rowsh[w][lane * 2]) = h2;
    __syncwarp();

    // GEMV1: a1 cols 2*lane, 2*lane+1 over Wf1 [64,64]
    float a0 = bf1[2 * lane], a1v = bf1[2 * lane + 1];
#pragma unroll 4
    for (int k = 0; k < 64; k++) {
        float h = rowsh[w][k];
        float2 wv = *reinterpret_cast<const float2*>(&Wf1sh[k * 64 + 2 * lane]);
        a0  += h * wv.x;
        a1v += h * wv.y;
    }
    a0  = tanhf(a0);
    a1v = tanhf(a1v);

    // GEMV2: s_d = bf2[d] + sum_j a1[j] * Wf2[j][d]; lane holds j = 2*lane, 2*lane+1
    float p[8];
#pragma unroll
    for (int d = 0; d < 8; d++) {
        float2 wv = *reinterpret_cast<const float2*>(&Wf2t[d * 64 + 2 * lane]);
        p[d] = a0 * wv.x + a1v * wv.y;
    }
#pragma unroll
    for (int off = 16; off > 0; off >>= 1)
#pragma unroll
        for (int d = 0; d < 8; d++) p[d] += __shfl_xor_sync(0xFFFFFFFF, p[d], off);

    if (lane < 8) {
        float e = expf(p[lane] + bf2[lane]);
        g_s[(size_t)node * 8 + lane] = e;
        atomicAdd(&g_Zstage[(node & 63) * 8 + lane], e);
    }
}

// ---------------- pooled reductions: G = e.T@h2, C = e.T@e --------------------
__global__ void k_accum(int n) {
    __shared__ float h2sh[64 * 64];
    __shared__ float esh[64 * 8];
    int tid = threadIdx.x;
    int c0  = blockIdx.x * 64;
    int nv  = n - c0;
    if (nv > 64) nv = 64;

    for (int t = tid; t < 64 * 64; t += 256) {
        int row = t >> 6;
        if (row < nv) h2sh[t] = g_h2[(size_t)(c0 + row) * 64 + (t & 63)];
    }
    for (int t = tid; t < 512; t += 256) {
        int row = t >> 3;
        if (row < nv) esh[t] = g_s[(size_t)(c0 + row) * 8 + (t & 7)];
    }
    __syncthreads();

    int p0 = tid, p1 = tid + 256;
    int d0 = p0 >> 6, h0 = p0 & 63;
    int d1 = p1 >> 6, h1 = p1 & 63;
    int cd1 = tid >> 3, cd2 = tid & 7;
    float aG0 = 0.f, aG1 = 0.f, aC = 0.f;
    for (int m = 0; m < nv; m++) {
        float* hrow = &h2sh[m * 64];
        float* erow = &esh[m * 8];
        aG0 += erow[d0] * hrow[h0];
        aG1 += erow[d1] * hrow[h1];
        if (tid < 64) aC += erow[cd1] * erow[cd2];
    }
    atomicAdd(&g_G[p0], aG0);
    atomicAdd(&g_G[p1], aG1);
    if (tid < 64) atomicAdd(&g_C[tid], aC);
}

// ---------------- final: normalize, penalty, dense head, log_softmax ----------
__global__ void k_final(const float* __restrict__ Wl, const float* __restrict__ bl,
                        float* __restrict__ out) {
    __shared__ float ge[512];
    __shared__ float Zs[8];
    __shared__ float tmp[16];
    __shared__ float lg[10];
    int tid = threadIdx.x; // 64 threads
    if (tid < 8) {
        float z = 0.f;
        for (int g = 0; g < 64; g++) z += g_Zstage[g * 8 + tid];
        Zs[tid] = z;
    }
    __syncthreads();
    for (int p = tid; p < 512; p += 64) {
        float v = g_G[p] / Zs[p >> 6];
        ge[p]  = v;
        out[p] = v;
    }
    __syncthreads();
    if (tid < 8) {
        float ss = 0.f;
        for (int d2 = 0; d2 < 8; d2++) {
            float c = g_C[tid * 8 + d2] / (Zs[tid] * Zs[d2]) - (tid == d2 ? 1.0f : 0.0f);
            ss += c * c;
        }
        tmp[tid] = sqrtf(ss);
    }
    __syncthreads();
    if (tid == 0) {
        float pen = 0.f;
        for (int d = 0; d < 8; d++) pen += tmp[d];
        out[512] = pen;
    }
    if (tid < 10) {
        float acc = bl[tid];
        for (int p = 0; p < 512; p++) acc += ge[p] * Wl[p * 10 + tid];
        lg[tid] = acc;
    }
    __syncthreads();
    if (tid == 0) {
        float m = lg[0];
        for (int l = 1; l < 10; l++) m = fmaxf(m, lg[l]);
        float s = 0.f;
        for (int l = 0; l < 10; l++) s += expf(lg[l] - m);
        tmp[0] = m + logf(s);
    }
    __syncthreads();
    if (tid < 10) out[513 + tid] = lg[tid] - tmp[0];
}

// ---------------- launch -------------------------------------------------------
extern "C" void kernel_launch(void* const* d_in, const int* in_sizes, int n_in,
                              void* d_out, int out_size) {
    const int*   edges = (const int*)d_in[0];
    const float* X     = (const float*)d_in[1];
    const float* W1    = (const float*)d_in[2];
    const float* b1    = (const float*)d_in[3];
    const float* W2    = (const float*)d_in[4];
    const float* b2    = (const float*)d_in[5];
    const float* Wf1   = (const float*)d_in[6];
    const float* bf1   = (const float*)d_in[7];
    const float* Wf2   = (const float*)d_in[8];
    const float* bf2   = (const float*)d_in[9];
    const float* Wl    = (const float*)d_in[10];
    const float* bl    = (const float*)d_in[11];
    float* out = (float*)d_out;

    int e = in_sizes[0] / 2;
    int n = in_sizes[1] / 128;
    const int* src = edges;
    const int* dst = edges + e;

    float *pHs1, *pH2s, *pH2;
    cudaGetSymbolAddress((void**)&pHs1, g_hs1);
    cudaGetSymbolAddress((void**)&pH2s, g_h2s);
    cudaGetSymbolAddress((void**)&pH2,  g_h2);

    const int T  = 256;
    const int NB = (n + 1023) / 1024;

    // CSR build + dinv
    k_init  <<<(n + T - 1) / T, T>>>(n);
    k_deg   <<<(e + T - 1) / T, T>>>(dst, e);
    k_scan1 <<<NB, 1024>>>(n);
    k_scan2 <<<1, 32>>>(NB);
    k_scan3 <<<NB, 1024>>>(n);
    k_bucket<<<(e + T - 1) / T, T>>>(src, dst, e);

    // layer 1 GEMM: hs1 = (X@W1)*dinv
    gemm1_kernel<<<(n + 127) / 128, T>>>(X, W1, pHs1, n);

    // fused: gather1 + relu + GEMV W2 -> h2s
    gather128_fused<<<(n + 7) / 8, T>>>(pHs1, b1, W2, pH2s, n);

    // fused: gather2 + bias + attention MLP -> h2, exp(s), Z partials
    gather64_fused<<<(n + 7) / 8, T>>>(pH2s, b2, Wf1, bf1, Wf2, bf2, pH2, n);

    // pooled reductions + head
    k_accum<<<(n + 63) / 64, T>>>(n);
    k_final<<<1, 64>>>(Wl, bl, out);
}

// round 4
// speedup vs baseline: 1.0947x; 1.0947x over previous
#include <cuda_runtime.h>
#include <math.h>

#define MAXN 100000
#define MAXE 3200000

// ---------------- scratch (static device globals; no allocation) -------------
__device__ float g_hs1 [(size_t)MAXN * 128]; // X@W1 (unscaled); later reused as a1
__device__ float g_h1  [(size_t)MAXN * 128]; // h1 (post conv1)
__device__ float g_h2s [(size_t)MAXN * 64];  // h1@W2 (unscaled)
__device__ float g_h2  [(size_t)MAXN * 64];  // h2 (post conv2)
__device__ float g_s   [(size_t)MAXN * 8];   // exp(attention logits)
__device__ float g_dinv[MAXN];               // deg^{-1/2}
__device__ int   g_cnt [MAXN];
__device__ int   g_tmp [MAXN];
__device__ int   g_off [MAXN + 1];
__device__ int   g_cur [MAXN];
__device__ int   g_ecsr[MAXE];
__device__ int   g_bsum[128];
__device__ int   g_bpre[128];
__device__ float g_Z[8];
__device__ float g_G[512];
__device__ float g_C[64];

// ---------------- init / degree / CSR build ----------------------------------
__global__ void k_init(int n) {
    int i = blockIdx.x * blockDim.x + threadIdx.x;
    if (i < n)   g_cnt[i] = 0;
    if (i < 512) g_G[i] = 0.0f;
    if (i < 64)  g_C[i] = 0.0f;
    if (i < 8)   g_Z[i] = 0.0f;
}

__global__ void k_deg(const int* __restrict__ dst, int e) {
    int i = blockIdx.x * blockDim.x + threadIdx.x;
    if (i < e) atomicAdd(&g_cnt[dst[i]], 1);
}

__global__ void k_scan1(int n) {
    __shared__ int sh[1024];
    int i = blockIdx.x * 1024 + threadIdx.x;
    int v = (i < n) ? g_cnt[i] : 0;
    if (i < n) g_dinv[i] = rsqrtf((float)(v + 1)); // +1 self loop
    sh[threadIdx.x] = v;
    __syncthreads();
#pragma unroll
    for (int off = 1; off < 1024; off <<= 1) {
        int t = (threadIdx.x >= off) ? sh[threadIdx.x - off] : 0;
        __syncthreads();
        sh[threadIdx.x] += t;
        __syncthreads();
    }
    if (i < n) g_tmp[i] = sh[threadIdx.x];
    if (threadIdx.x == 1023) g_bsum[blockIdx.x] = sh[1023];
}

__global__ void k_scan2(int nb) { // one block, 128 threads, nb <= 128
    int t = threadIdx.x;
    int orig = (t < nb) ? g_bsum[t] : 0;
    int v = orig;
#pragma unroll
    for (int off = 1; off < 32; off <<= 1) {
        int u = __shfl_up_sync(0xFFFFFFFF, v, off);
        if ((t & 31) >= off) v += u;
    }
    __shared__ int ws[4];
    if ((t & 31) == 31) ws[t >> 5] = v;
    __syncthreads();
    int add = 0;
    for (int w = 0; w < (t >> 5); w++) add += ws[w];
    v += add;
    if (t < nb) g_bpre[t] = v - orig; // exclusive
}

__global__ void k_scan3(int n) {
    int i = blockIdx.x * 1024 + threadIdx.x;
    if (i < n) {
        int inc = g_tmp[i] + g_bpre[blockIdx.x];
        g_off[i + 1] = inc;
        g_cur[i]     = inc - g_cnt[i];
    }
    if (i == 0) g_off[0] = 0;
}

__global__ void k_bucket(const int* __restrict__ src, const int* __restrict__ dst, int e) {
    int i = blockIdx.x * blockDim.x + threadIdx.x;
    if (i < e) {
        int d   = dst[i];
        int pos = atomicAdd(&g_cur[d], 1);
        g_ecsr[pos] = src[i];
    }
}

// ---------------- 8x8 register-tiled GEMM, W resident in smem -----------------
// out[i,:] = A[i,:] @ W        (TANH=false)
// out[i,:] = tanh(A@W + bias)  (TANH=true)
template <int K, int C, int BM, bool TANH>
__global__ void __launch_bounds__(256, 2)
gemm_ws(const float* __restrict__ A, const float* __restrict__ W,
        const float* __restrict__ bias, float* __restrict__ out, int n) {
    constexpr int KC   = 16;
    constexpr int NCG  = C / 8;       // col groups
    constexpr int BMP  = BM + 4;      // padded row stride in Ash
    constexpr int PASS = BM / 64;     // A-loader passes
    constexpr int NCH  = K / KC;

    extern __shared__ float smem[];
    float* Wsh = smem;                 // K*C
    float* Ash = smem + K * C;         // 2 * KC * BMP

    int tid = threadIdx.x;
    int m0  = blockIdx.x * BM;

    for (int t = tid; t < K * C / 4; t += 256)
        reinterpret_cast<float4*>(Wsh)[t] = reinterpret_cast<const float4*>(W)[t];

    int q     = tid & 3;
    int rbase = tid >> 2;
    int tc    = tid % NCG;
    int tr    = tid / NCG;

    float bv[8];
    if (TANH) {
#pragma unroll
        for (int j = 0; j < 8; j++) bv[j] = bias[tc * 8 + j];
    }

    float acc[8][8];
#pragma unroll
    for (int i = 0; i < 8; i++)
#pragma unroll
        for (int j = 0; j < 8; j++) acc[i][j] = 0.0f;

    float4 pref[PASS];
    // load first chunk
#pragma unroll
    for (int p = 0; p < PASS; p++) {
        int row = m0 + rbase + p * 64;
        pref[p] = (row < n)
            ? *reinterpret_cast<const float4*>(&A[(size_t)row * K + q * 4])
            : make_float4(0.f, 0.f, 0.f, 0.f);
    }
    {
        float* db = Ash;
#pragma unroll
        for (int p = 0; p < PASS; p++) {
            int r = rbase + p * 64;
            db[(q * 4 + 0) * BMP + r] = pref[p].x;
            db[(q * 4 + 1) * BMP + r] = pref[p].y;
            db[(q * 4 + 2) * BMP + r] = pref[p].z;
            db[(q * 4 + 3) * BMP + r] = pref[p].w;
        }
    }
    __syncthreads();

    for (int ch = 0; ch < NCH; ch++) {
        if (ch + 1 < NCH) {
            int kc = (ch + 1) * KC;
#pragma unroll
            for (int p = 0; p < PASS; p++) {
                int row = m0 + rbase + p * 64;
                pref[p] = (row < n)
                    ? *reinterpret_cast<const float4*>(&A[(size_t)row * K + kc + q * 4])
                    : make_float4(0.f, 0.f, 0.f, 0.f);
            }
        }
        const float* Acur = Ash + (ch & 1) * (KC * BMP);
        const float* Wcur = Wsh + ch * KC * C;
#pragma unroll
        for (int k = 0; k < KC; k++) {
            float ar[8], br[8];
            *reinterpret_cast<float4*>(&ar[0]) =
                *reinterpret_cast<const float4*>(&Acur[k * BMP + tr * 8]);
            *reinterpret_cast<float4*>(&ar[4]) =
                *reinterpret_cast<const float4*>(&Acur[k * BMP + tr * 8 + 4]);
            *reinterpret_cast<float4*>(&br[0]) =
                *reinterpret_cast<const float4*>(&Wcur[k * C + tc * 8]);
            *reinterpret_cast<float4*>(&br[4]) =
                *reinterpret_cast<const float4*>(&Wcur[k * C + tc * 8 + 4]);
#pragma unroll
            for (int i = 0; i < 8; i++)
#pragma unroll
                for (int j = 0; j < 8; j++)
                    acc[i][j] += ar[i] * br[j];
        }
        if (ch + 1 < NCH) {
            float* db = Ash + ((ch + 1) & 1) * (KC * BMP);
#pragma unroll
            for (int p = 0; p < PASS; p++) {
                int r = rbase + p * 64;
                db[(q * 4 + 0) * BMP + r] = pref[p].x;
                db[(q * 4 + 1) * BMP + r] = pref[p].y;
                db[(q * 4 + 2) * BMP + r] = pref[p].z;
                db[(q * 4 + 3) * BMP + r] = pref[p].w;
            }
        }
        __syncthreads();
    }

#pragma unroll
    for (int i = 0; i < 8; i++) {
        int row = m0 + tr * 8 + i;
        if (row >= n) continue;
        float4 o0, o1;
        if (TANH) {
            o0.x = tanhf(acc[i][0] + bv[0]); o0.y = tanhf(acc[i][1] + bv[1]);
            o0.z = tanhf(acc[i][2] + bv[2]); o0.w = tanhf(acc[i][3] + bv[3]);
            o1.x = tanhf(acc[i][4] + bv[4]); o1.y = tanhf(acc[i][5] + bv[5]);
            o1.z = tanhf(acc[i][6] + bv[6]); o1.w = tanhf(acc[i][7] + bv[7]);
        } else {
            o0 = make_float4(acc[i][0], acc[i][1], acc[i][2], acc[i][3]);
            o1 = make_float4(acc[i][4], acc[i][5], acc[i][6], acc[i][7]);
        }
        size_t base = (size_t)row * C + tc * 8;
        *reinterpret_cast<float4*>(&out[base])     = o0;
        *reinterpret_cast<float4*>(&out[base + 4]) = o1;
    }
}

// ---------------- CSR gather aggregation (per-edge dinv) ----------------------
// acc = dinv[node]*hs[node] + sum dinv[s]*hs[s];  out = relu?(acc*dinv[node] + b)
__global__ void gather128(const float* __restrict__ hs, const float* __restrict__ b1,
                          float* __restrict__ out, int n) {
    int warp = (blockIdx.x * blockDim.x + threadIdx.x) >> 5;
    int lane = threadIdx.x & 31;
    if (warp >= n) return;
    const int node = warp;
    float dn = g_dinv[node];
    float4 v = *reinterpret_cast<const float4*>(&hs[(size_t)node * 128 + lane * 4]);
    float4 acc = make_float4(v.x * dn, v.y * dn, v.z * dn, v.w * dn);
    int j = g_off[node], jend = g_off[node + 1];
    for (; j + 2 <= jend; j += 2) {
        int s0 = __ldg(&g_ecsr[j]);
        int s1 = __ldg(&g_ecsr[j + 1]);
        float d0 = __ldg(&g_dinv[s0]);
        float d1 = __ldg(&g_dinv[s1]);
        float4 v0 = *reinterpret_cast<const float4*>(&hs[(size_t)s0 * 128 + lane * 4]);
        float4 v1 = *reinterpret_cast<const float4*>(&hs[(size_t)s1 * 128 + lane * 4]);
        acc.x += v0.x * d0 + v1.x * d1; acc.y += v0.y * d0 + v1.y * d1;
        acc.z += v0.z * d0 + v1.z * d1; acc.w += v0.w * d0 + v1.w * d1;
    }
    if (j < jend) {
        int s0 = __ldg(&g_ecsr[j]);
        float d0 = __ldg(&g_dinv[s0]);
        float4 v0 = *reinterpret_cast<const float4*>(&hs[(size_t)s0 * 128 + lane * 4]);
        acc.x += v0.x * d0; acc.y += v0.y * d0; acc.z += v0.z * d0; acc.w += v0.w * d0;
    }
    float4 bb = *reinterpret_cast<const float4*>(&b1[lane * 4]);
    float4 o = make_float4(fmaxf(acc.x * dn + bb.x, 0.f), fmaxf(acc.y * dn + bb.y, 0.f),
                           fmaxf(acc.z * dn + bb.z, 0.f), fmaxf(acc.w * dn + bb.w, 0.f));
    *reinterpret_cast<float4*>(&out[(size_t)node * 128 + lane * 4]) = o;
}

__global__ void gather64(const float* __restrict__ hs, const float* __restrict__ b2,
                         float* __restrict__ out, int n) {
    int warp = (blockIdx.x * blockDim.x + threadIdx.x) >> 5;
    int lane = threadIdx.x & 31;
    if (warp >= n) return;
    const int node = warp;
    float dn = g_dinv[node];
    float2 v = *reinterpret_cast<const float2*>(&hs[(size_t)node * 64 + lane * 2]);
    float2 acc = make_float2(v.x * dn, v.y * dn);
    int j = g_off[node], jend = g_off[node + 1];
    for (; j + 2 <= jend; j += 2) {
        int s0 = __ldg(&g_ecsr[j]);
        int s1 = __ldg(&g_ecsr[j + 1]);
        float d0 = __ldg(&g_dinv[s0]);
        float d1 = __ldg(&g_dinv[s1]);
        float2 v0 = *reinterpret_cast<const float2*>(&hs[(size_t)s0 * 64 + lane * 2]);
        float2 v1 = *reinterpret_cast<const float2*>(&hs[(size_t)s1 * 64 + lane * 2]);
        acc.x += v0.x * d0 + v1.x * d1; acc.y += v0.y * d0 + v1.y * d1;
    }
    if (j < jend) {
        int s0 = __ldg(&g_ecsr[j]);
        float d0 = __ldg(&g_dinv[s0]);
        float2 v0 = *reinterpret_cast<const float2*>(&hs[(size_t)s0 * 64 + lane * 2]);
        acc.x += v0.x * d0; acc.y += v0.y * d0;
    }
    float2 bb = *reinterpret_cast<const float2*>(&b2[lane * 2]);
    float2 o = make_float2(acc.x * dn + bb.x, acc.y * dn + bb.y);
    *reinterpret_cast<float2*>(&out[(size_t)node * 64 + lane * 2]) = o;
}

// ---------------- attention logits -> exp(s), fused Z accumulation ------------
__global__ void k_logits(const float* __restrict__ a1, const float* __restrict__ Wf2,
                         const float* __restrict__ bf2, int n) {
    __shared__ float Wsh[64 * 8];
    __shared__ float bsh[8];
    __shared__ float red[256];
    int tid = threadIdx.x;
    for (int t = tid; t < 512; t += 256) Wsh[t] = Wf2[t];
    if (tid < 8) bsh[tid] = bf2[tid];
    __syncthreads();

    int node = blockIdx.x * 32 + (tid >> 3);
    int d    = tid & 7;
    float e  = 0.0f;
    if (node < n) {
        float acc = bsh[d];
        const float* ar = a1 + (size_t)node * 64;
#pragma unroll 8
        for (int j = 0; j < 64; j++) acc += ar[j] * Wsh[j * 8 + d];
        e = expf(acc);
        g_s[(size_t)node * 8 + d] = e;
    }
    red[tid] = e;
    __syncthreads();
    for (int off = 128; off >= 8; off >>= 1) {
        if (tid < off) red[tid] += red[tid + off];
        __syncthreads();
    }
    if (tid < 8) atomicAdd(&g_Z[tid], red[tid]);
}

// ---------------- pooled reductions: G = e.T@h2, C = e.T@e --------------------
__global__ void k_accum(int n) {
    __shared__ float h2sh[64 * 64];
    __shared__ float esh[64 * 8];
    int tid = threadIdx.x;
    int c0  = blockIdx.x * 64;
    int nv  = n - c0;
    if (nv > 64) nv = 64;

    for (int t = tid; t < 64 * 64; t += 256) {
        int row = t >> 6;
        if (row < nv) h2sh[t] = g_h2[(size_t)(c0 + row) * 64 + (t & 63)];
    }
    for (int t = tid; t < 512; t += 256) {
        int row = t >> 3;
        if (row < nv) esh[t] = g_s[(size_t)(c0 + row) * 8 + (t & 7)];
    }
    __syncthreads();

    int p0 = tid, p1 = tid + 256;
    int d0 = p0 >> 6, h0 = p0 & 63;
    int d1 = p1 >> 6, h1 = p1 & 63;
    int cd1 = tid >> 3, cd2 = tid & 7;
    float aG0 = 0.f, aG1 = 0.f, aC = 0.f;
    for (int m = 0; m < nv; m++) {
        float* hrow = &h2sh[m * 64];
        float* erow = &esh[m * 8];
        aG0 += erow[d0] * hrow[h0];
        aG1 += erow[d1] * hrow[h1];
        if (tid < 64) aC += erow[cd1] * erow[cd2];
    }
    atomicAdd(&g_G[p0], aG0);
    atomicAdd(&g_G[p1], aG1);
    if (tid < 64) atomicAdd(&g_C[tid], aC);
}

// ---------------- final: normalize, penalty, dense head, log_softmax ----------
__global__ void k_final(const float* __restrict__ Wl, const float* __restrict__ bl,
                        float* __restrict__ out) {
    __shared__ float ge[512];
    __shared__ float Zs[8];
    __shared__ float tmp[16];
    __shared__ float lg[10];
    int tid = threadIdx.x; // 64 threads
    if (tid < 8) Zs[tid] = g_Z[tid];
    __syncthreads();
    for (int p = tid; p < 512; p += 64) {
        float v = g_G[p] / Zs[p >> 6];
        ge[p]  = v;
        out[p] = v;
    }
    __syncthreads();
    if (tid < 8) {
        float ss = 0.f;
        for (int d2 = 0; d2 < 8; d2++) {
            float c = g_C[tid * 8 + d2] / (Zs[tid] * Zs[d2]) - (tid == d2 ? 1.0f : 0.0f);
            ss += c * c;
        }
        tmp[tid] = sqrtf(ss);
    }
    __syncthreads();
    if (tid == 0) {
        float pen = 0.f;
        for (int d = 0; d < 8; d++) pen += tmp[d];
        out[512] = pen;
    }
    if (tid < 10) {
        float acc = bl[tid];
        for (int p = 0; p < 512; p++) acc += ge[p] * Wl[p * 10 + tid];
        lg[tid] = acc;
    }
    __syncthreads();
    if (tid == 0) {
        float m = lg[0];
        for (int l = 1; l < 10; l++) m = fmaxf(m, lg[l]);
        float s = 0.f;
        for (int l = 0; l < 10; l++) s += expf(lg[l] - m);
        tmp[0] = m + logf(s);
    }
    __syncthreads();
    if (tid < 10) out[513 + tid] = lg[tid] - tmp[0];
}

// ---------------- launch -------------------------------------------------------
extern "C" void kernel_launch(void* const* d_in, const int* in_sizes, int n_in,
                              void* d_out, int out_size) {
    const int*   edges = (const int*)d_in[0];
    const float* X     = (const float*)d_in[1];
    const float* W1    = (const float*)d_in[2];
    const float* b1    = (const float*)d_in[3];
    const float* W2    = (const float*)d_in[4];
    const float* b2    = (const float*)d_in[5];
    const float* Wf1   = (const float*)d_in[6];
    const float* bf1   = (const float*)d_in[7];
    const float* Wf2   = (const float*)d_in[8];
    const float* bf2   = (const float*)d_in[9];
    const float* Wl    = (const float*)d_in[10];
    const float* bl    = (const float*)d_in[11];
    float* out = (float*)d_out;

    int e = in_sizes[0] / 2;
    int n = in_sizes[1] / 128;
    const int* src = edges;
    const int* dst = edges + e;

    float *pHs1, *pH1, *pH2s, *pH2;
    cudaGetSymbolAddress((void**)&pHs1, g_hs1);
    cudaGetSymbolAddress((void**)&pH1,  g_h1);
    cudaGetSymbolAddress((void**)&pH2s, g_h2s);
    cudaGetSymbolAddress((void**)&pH2,  g_h2);
    float* pA1 = pHs1; // reuse hs1 buffer for a1

    // one-time setup: side stream, events, smem limits
    static cudaStream_t sCsr = nullptr;
    static cudaEvent_t evRoot = nullptr, evCsr = nullptr;
    const int SM1 = (128 * 128 + 2 * 16 * (128 + 4)) * 4; // 82432
    const int SM2 = (128 * 64  + 2 * 16 * (256 + 4)) * 4; // 66048
    const int SM3 = (64 * 64   + 2 * 16 * (256 + 4)) * 4; // 49664
    if (!sCsr) {
        cudaStreamCreateWithFlags(&sCsr, cudaStreamNonBlocking);
        cudaEventCreateWithFlags(&evRoot, cudaEventDisableTiming);
        cudaEventCreateWithFlags(&evCsr, cudaEventDisableTiming);
        cudaFuncSetAttribute((const void*)gemm_ws<128, 128, 128, false>,
                             cudaFuncAttributeMaxDynamicSharedMemorySize, SM1);
        cudaFuncSetAttribute((const void*)gemm_ws<128, 64, 256, false>,
                             cudaFuncAttributeMaxDynamicSharedMemorySize, SM2);
        cudaFuncSetAttribute((const void*)gemm_ws<64, 64, 256, true>,
                             cudaFuncAttributeMaxDynamicSharedMemorySize, SM3);
    }

    const int T  = 256;
    const int NB = (n + 1023) / 1024;

    // fork: CSR build on side stream, gemm1 on main stream (independent)
    cudaEventRecord(evRoot, 0);
    cudaStreamWaitEvent(sCsr, evRoot, 0);
    k_init  <<<(n + T - 1) / T, T, 0, sCsr>>>(n);
    k_deg   <<<(e + T - 1) / T, T, 0, sCsr>>>(dst, e);
    k_scan1 <<<NB, 1024, 0, sCsr>>>(n);
    k_scan2 <<<1, 128, 0, sCsr>>>(NB);
    k_scan3 <<<NB, 1024, 0, sCsr>>>(n);
    k_bucket<<<(e + T - 1) / T, T, 0, sCsr>>>(src, dst, e);
    cudaEventRecord(evCsr, sCsr);

    // main stream: layer-1 GEMM (no dinv dependency now)
    gemm_ws<128, 128, 128, false><<<(n + 127) / 128, T, SM1>>>(X, W1, nullptr, pHs1, n);

    // join, then the dependent chain
    cudaStreamWaitEvent(0, evCsr, 0);
    gather128<<<(n + 7) / 8, T>>>(pHs1, b1, pH1, n);
    gemm_ws<128, 64, 256, false><<<(n + 255) / 256, T, SM2>>>(pH1, W2, nullptr, pH2s, n);
    gather64<<<(n + 7) / 8, T>>>(pH2s, b2, pH2, n);
    gemm_ws<64, 64, 256, true><<<(n + 255) / 256, T, SM3>>>(pH2, Wf1, bf1, pA1, n);
    k_logits<<<(n + 31) / 32, T>>>(pA1, Wf2, bf2, n);
    k_accum <<<(n + 63) / 64, T>>>(n);
    k_final <<<1, 64>>>(Wl, bl, out);
}